// round 3
// baseline (speedup 1.0000x reference)
#include <cuda_runtime.h>
#include <math.h>

#define AG    10
#define SEQ   50
#define IND   6
#define HID   64
#define OUTD  2
#define TDEC  60
#define BATCH 32768

#define NG      256   // 4*HID gate columns
#define MT      64    // batch rows per CTA
#define THREADS 256
#define AST     68    // A staging row stride in floats (pad vs 64)
#define KC      16    // K-chunk rows for weight streaming

// Logical K per section and padded (multiple of KC) row counts
#define KE0 71
#define KE1 129
#define KD0 67
#define KD1 129
#define PE0 80
#define PE1 144
#define PD0 80
#define PD1 144

#define OFF_E0 0
#define OFF_E1 (PE0*NG)
#define OFF_D0 ((PE0+PE1)*NG)
#define OFF_D1 ((PE0+PE1+PD0)*NG)
#define WTOT   ((PE0+PE1+PD0+PD1)*NG)

// Pre-permuted, bias-folded weight scratch (gate-interleaved columns).
__device__ __align__(16) float g_W[WTOT];

// ---------------------------------------------------------------------------
// Prep kernel: build g_W.
// Column n = 4*j + q maps to gate row r = q*64 + j  (q: 0=i,1=f,2=g,3=o).
// Row 0 of each section = combined bias (A supplies a row of ones).
// ---------------------------------------------------------------------------
__global__ void prep_kernel(
    const float* __restrict__ eWih0, const float* __restrict__ eWhh0,
    const float* __restrict__ ebih0, const float* __restrict__ ebhh0,
    const float* __restrict__ eWih1, const float* __restrict__ eWhh1,
    const float* __restrict__ ebih1, const float* __restrict__ ebhh1,
    const float* __restrict__ dWih0, const float* __restrict__ dWhh0,
    const float* __restrict__ dbih0, const float* __restrict__ dbhh0,
    const float* __restrict__ dWih1, const float* __restrict__ dWhh1,
    const float* __restrict__ dbih1, const float* __restrict__ dbhh1)
{
    int idx = blockIdx.x * blockDim.x + threadIdx.x;
    if (idx >= WTOT) return;
    int n    = idx & (NG - 1);
    int grow = idx >> 8;
    int r    = ((n & 3) << 6) | (n >> 2);
    float v = 0.f;
    if (grow < PE0) {
        int row = grow;
        if      (row == 0)  v = ebih0[r] + ebhh0[r];
        else if (row <= 6)  v = eWih0[r * IND + (row - 1)];
        else if (row <= 70) v = eWhh0[r * HID + (row - 7)];
    } else if (grow < PE0 + PE1) {
        int row = grow - PE0;
        if      (row == 0)   v = ebih1[r] + ebhh1[r];
        else if (row <= 64)  v = eWih1[r * HID + (row - 1)];
        else if (row <= 128) v = eWhh1[r * HID + (row - 65)];
    } else if (grow < PE0 + PE1 + PD0) {
        int row = grow - (PE0 + PE1);
        if      (row == 0)  v = dbih0[r] + dbhh0[r];
        else if (row <= 2)  v = dWih0[r * OUTD + (row - 1)];
        else if (row <= 66) v = dWhh0[r * HID + (row - 3)];
    } else {
        int row = grow - (PE0 + PE1 + PD0);
        if      (row == 0)   v = dbih1[r] + dbhh1[r];
        else if (row <= 64)  v = dWih1[r * HID + (row - 1)];
        else if (row <= 128) v = dWhh1[r * HID + (row - 65)];
    }
    g_W[idx] = v;
}

// ---------------------------------------------------------------------------
// Device helpers
// ---------------------------------------------------------------------------
__device__ __forceinline__ float sigmf(float x) {
    return __fdividef(1.f, 1.f + __expf(-x));
}
// Robust tanh: 1 - 2/(e^{2x}+1). Handles |x| large without NaN.
__device__ __forceinline__ float tanhf_(float x) {
    float e = __expf(2.f * x);
    return 1.f - __fdividef(2.f, e + 1.f);
}

// GEMM: acc[8][8] += A[K x 64]^T-tiled * B[K x 256], B streamed from g_W
// through SMEM chunk Bs (16 rows) with register double-buffering.
__device__ __forceinline__ void do_gemm(const float* __restrict__ Bg, int K,
                                        const float* __restrict__ A,
                                        float* __restrict__ Bs,
                                        float (&acc)[8][8],
                                        int tid, int tm0, int tn0)
{
    const int nch = (K + KC - 1) >> 4;
    const float4* __restrict__ Bgv = (const float4*)Bg;
    float4* Bsv = (float4*)Bs;
    float4 p0 = Bgv[tid], p1 = Bgv[256 + tid], p2 = Bgv[512 + tid], p3 = Bgv[768 + tid];
    Bsv[tid] = p0; Bsv[256 + tid] = p1; Bsv[512 + tid] = p2; Bsv[768 + tid] = p3;
    __syncthreads();
    for (int c = 0; c < nch; c++) {
        if (c + 1 < nch) {
            const float4* q = Bgv + (size_t)(c + 1) * 1024;
            p0 = q[tid]; p1 = q[256 + tid]; p2 = q[512 + tid]; p3 = q[768 + tid];
        }
        const int kc   = c * KC;
        const int kend = min(KC, K - kc);
        const float* Abase = A + (size_t)kc * AST;
        #pragma unroll 4
        for (int kk = 0; kk < kend; kk++) {
            float4 a0 = *(const float4*)(Abase + kk * AST + tm0);
            float4 a1 = *(const float4*)(Abase + kk * AST + tm0 + 4);
            float4 b0 = *(const float4*)(Bs + kk * NG + tn0);
            float4 b1 = *(const float4*)(Bs + kk * NG + tn0 + 4);
            float av[8] = {a0.x, a0.y, a0.z, a0.w, a1.x, a1.y, a1.z, a1.w};
            float bv[8] = {b0.x, b0.y, b0.z, b0.w, b1.x, b1.y, b1.z, b1.w};
            #pragma unroll
            for (int i = 0; i < 8; i++)
                #pragma unroll
                for (int j = 0; j < 8; j++)
                    acc[i][j] = fmaf(av[i], bv[j], acc[i][j]);
        }
        __syncthreads();
        if (c + 1 < nch) {
            Bsv[tid] = p0; Bsv[256 + tid] = p1; Bsv[512 + tid] = p2; Bsv[768 + tid] = p3;
            __syncthreads();
        }
    }
}

// LSTM gate update. Thread owns 8 rows x 2 hidden cols (complete i,f,g,o quads
// thanks to the gate-interleaved weight permutation). c stays in registers.
template <bool L0>
__device__ __forceinline__ void do_update(float (&acc)[8][8], float (&cst)[8][2],
                                          float* __restrict__ A1w,
                                          float* __restrict__ A0w, int xoff,
                                          int lane, int tm0)
{
    #pragma unroll
    for (int i = 0; i < 8; i++) {
        #pragma unroll
        for (int jj = 0; jj < 2; jj++) {
            float gi = acc[i][jj * 4 + 0];
            float gf = acc[i][jj * 4 + 1];
            float gg = acc[i][jj * 4 + 2];
            float go = acc[i][jj * 4 + 3];
            float c = sigmf(gf) * cst[i][jj] + sigmf(gi) * tanhf_(gg);
            cst[i][jj] = c;
            float h = sigmf(go) * tanhf_(c);
            int j = lane * 2 + jj;
            int m = tm0 + i;
            if (L0) {
                A1w[(1 + j) * AST + m]    = h;   // layer-1 input slot
                A0w[(xoff + j) * AST + m] = h;   // own recurrence slot
            } else {
                A1w[(65 + j) * AST + m]   = h;   // own recurrence slot
            }
        }
    }
}

#define ZERO_ACC(acc) do {                          \
    _Pragma("unroll")                               \
    for (int _i = 0; _i < 8; _i++)                  \
        _Pragma("unroll")                           \
        for (int _j = 0; _j < 8; _j++)              \
            (acc)[_i][_j] = 0.f;                    \
} while (0)

// ---------------------------------------------------------------------------
// Main persistent-per-tile LSTM kernel. One CTA = 64 batch rows, full
// encoder + decoder recurrence with states resident in registers/SMEM.
// ---------------------------------------------------------------------------
__global__ void __launch_bounds__(THREADS)
lstm_main(const float* __restrict__ hist, const float* __restrict__ linW,
          const float* __restrict__ linb, const float* __restrict__ start,
          float* __restrict__ out)
{
    extern __shared__ float sm[];
    float* A0 = sm;                    // [KE0][AST]  layer0 input staging
    float* A1 = A0 + KE0 * AST;        // [KE1][AST]  layer1 input staging
    float* Bs = A1 + KE1 * AST;        // [KC][NG]    weight chunk
    float* lw = Bs + KC * NG;          // [2][64]     lin_W
    float* lb = lw + 128;              // [2]         lin_b

    const int tid  = threadIdx.x;
    const int lane = tid & 31;
    const int tm0  = (tid >> 5) * 8;
    const int tn0  = lane * 8;
    const int b0   = blockIdx.x * MT;

    for (int i = tid; i < KE0 * AST; i += THREADS) A0[i] = 0.f;
    for (int i = tid; i < KE1 * AST; i += THREADS) A1[i] = 0.f;
    if (tid < MT) { A0[tid] = 1.f; A1[tid] = 1.f; }   // ones row (bias feed)
    if (tid < 128) lw[tid] = linW[tid];
    if (tid < 2)   lb[tid] = linb[tid];

    float cs[2][8][2];
    #pragma unroll
    for (int L = 0; L < 2; L++)
        #pragma unroll
        for (int i = 0; i < 8; i++)
            #pragma unroll
            for (int jj = 0; jj < 2; jj++)
                cs[L][i][jj] = 0.f;
    __syncthreads();

    // ---------------- encoder: 50 steps ----------------
    for (int t = 0; t < SEQ; t++) {
        if (tid < MT) {
            const float* xp = hist + (size_t)(b0 + tid) * (AG * SEQ * IND) + t * IND;
            #pragma unroll
            for (int i = 0; i < IND; i++) A0[(1 + i) * AST + tid] = xp[i];
        }
        __syncthreads();
        float acc[8][8];
        ZERO_ACC(acc);
        do_gemm(g_W + OFF_E0, KE0, A0, Bs, acc, tid, tm0, tn0);
        do_update<true>(acc, cs[0], A1, A0, 7, lane, tm0);
        __syncthreads();
        ZERO_ACC(acc);
        do_gemm(g_W + OFF_E1, KE1, A1, Bs, acc, tid, tm0, tn0);
        do_update<false>(acc, cs[1], A1, A0, 0, lane, tm0);
        // next iter's loadx + sync provides the barrier before reuse
    }

    // -------- phase switch: shift h0 rows 7..70 -> 3..66, set start token ----
    {
        float tmp[16];
        #pragma unroll
        for (int e = 0; e < 16; e++) {
            int idx = tid + e * THREADS;       // 0..4095
            int k = idx >> 6, m = idx & 63;
            tmp[e] = A0[(7 + k) * AST + m];
        }
        __syncthreads();
        #pragma unroll
        for (int e = 0; e < 16; e++) {
            int idx = tid + e * THREADS;
            int k = idx >> 6, m = idx & 63;
            A0[(3 + k) * AST + m] = tmp[e];
        }
        if (tid < 128) {
            int o = tid >> 6, m = tid & 63;
            A0[(1 + o) * AST + m] = start[o];
        }
        __syncthreads();
    }

    // ---------------- decoder: 60 steps ----------------
    for (int t = 0; t < TDEC; t++) {
        float acc[8][8];
        ZERO_ACC(acc);
        do_gemm(g_W + OFF_D0, KD0, A0, Bs, acc, tid, tm0, tn0);
        do_update<true>(acc, cs[0], A1, A0, 3, lane, tm0);
        __syncthreads();
        ZERO_ACC(acc);
        do_gemm(g_W + OFF_D1, KD1, A1, Bs, acc, tid, tm0, tn0);
        do_update<false>(acc, cs[1], A1, A0, 0, lane, tm0);
        __syncthreads();
        // out = h1 @ lin_W^T + lin_b ; feed back as next x; store result
        if (tid < 128) {
            int o = tid >> 6, m = tid & 63;
            float s = lb[o];
            const float* lwo = lw + o * 64;
            #pragma unroll 8
            for (int k = 0; k < HID; k++)
                s = fmaf(lwo[k], A1[(65 + k) * AST + m], s);
            out[(size_t)(b0 + m) * (TDEC * OUTD) + t * OUTD + o] = s;
            A0[(1 + o) * AST + m] = s;
        }
        __syncthreads();
    }
}

// ---------------------------------------------------------------------------
// Launch
// ---------------------------------------------------------------------------
extern "C" void kernel_launch(void* const* d_in, const int* in_sizes, int n_in,
                              void* d_out, int out_size)
{
    (void)in_sizes; (void)n_in; (void)out_size;
    const float* hist = (const float*)d_in[0];

    prep_kernel<<<(WTOT + 255) / 256, 256>>>(
        (const float*)d_in[1],  (const float*)d_in[2],
        (const float*)d_in[3],  (const float*)d_in[4],
        (const float*)d_in[5],  (const float*)d_in[6],
        (const float*)d_in[7],  (const float*)d_in[8],
        (const float*)d_in[9],  (const float*)d_in[10],
        (const float*)d_in[11], (const float*)d_in[12],
        (const float*)d_in[13], (const float*)d_in[14],
        (const float*)d_in[15], (const float*)d_in[16]);

    size_t smem = (size_t)(KE0 * AST + KE1 * AST + KC * NG + 132) * sizeof(float);
    cudaFuncSetAttribute(lstm_main, cudaFuncAttributeMaxDynamicSharedMemorySize,
                         (int)smem);
    lstm_main<<<BATCH / MT, THREADS, smem>>>(
        hist, (const float*)d_in[17], (const float*)d_in[18],
        (const float*)d_in[19], (float*)d_out);
}

// round 4
// speedup vs baseline: 1.0637x; 1.0637x over previous
#include <cuda_runtime.h>
#include <math.h>

#define AG    10
#define SEQ   50
#define IND   6
#define HID   64
#define OUTD  2
#define TDEC  60
#define BATCH 32768

#define NG      256   // 4*HID gate columns
#define MT      64    // batch rows per CTA
#define THREADS 256
#define AST     68    // A staging row stride in floats (pad vs 64)
#define KC      16    // K-chunk rows for weight streaming

// Logical K per section and padded (multiple of KC) row counts
#define KE0 71
#define KE1 129
#define KD0 67
#define KD1 129
#define PE0 80
#define PE1 144
#define PD0 80
#define PD1 144

#define OFF_E0 0
#define OFF_E1 (PE0*NG)
#define OFF_D0 ((PE0+PE1)*NG)
#define OFF_D1 ((PE0+PE1+PD0)*NG)
#define WTOT   ((PE0+PE1+PD0+PD1)*NG)

typedef unsigned long long u64t;

// Pre-permuted, bias-folded weight scratch (gate-interleaved columns).
__device__ __align__(16) float g_W[WTOT];

// ---------------------------------------------------------------------------
// Prep kernel: build g_W.
// Column n = 4*j + q maps to gate row r = q*64 + j  (q: 0=i,1=f,2=g,3=o).
// Row 0 of each section = combined bias (A supplies a row of ones).
// ---------------------------------------------------------------------------
__global__ void prep_kernel(
    const float* __restrict__ eWih0, const float* __restrict__ eWhh0,
    const float* __restrict__ ebih0, const float* __restrict__ ebhh0,
    const float* __restrict__ eWih1, const float* __restrict__ eWhh1,
    const float* __restrict__ ebih1, const float* __restrict__ ebhh1,
    const float* __restrict__ dWih0, const float* __restrict__ dWhh0,
    const float* __restrict__ dbih0, const float* __restrict__ dbhh0,
    const float* __restrict__ dWih1, const float* __restrict__ dWhh1,
    const float* __restrict__ dbih1, const float* __restrict__ dbhh1)
{
    int idx = blockIdx.x * blockDim.x + threadIdx.x;
    if (idx >= WTOT) return;
    int n    = idx & (NG - 1);
    int grow = idx >> 8;
    int r    = ((n & 3) << 6) | (n >> 2);
    float v = 0.f;
    if (grow < PE0) {
        int row = grow;
        if      (row == 0)  v = ebih0[r] + ebhh0[r];
        else if (row <= 6)  v = eWih0[r * IND + (row - 1)];
        else if (row <= 70) v = eWhh0[r * HID + (row - 7)];
    } else if (grow < PE0 + PE1) {
        int row = grow - PE0;
        if      (row == 0)   v = ebih1[r] + ebhh1[r];
        else if (row <= 64)  v = eWih1[r * HID + (row - 1)];
        else if (row <= 128) v = eWhh1[r * HID + (row - 65)];
    } else if (grow < PE0 + PE1 + PD0) {
        int row = grow - (PE0 + PE1);
        if      (row == 0)  v = dbih0[r] + dbhh0[r];
        else if (row <= 2)  v = dWih0[r * OUTD + (row - 1)];
        else if (row <= 66) v = dWhh0[r * HID + (row - 3)];
    } else {
        int row = grow - (PE0 + PE1 + PD0);
        if      (row == 0)   v = dbih1[r] + dbhh1[r];
        else if (row <= 64)  v = dWih1[r * HID + (row - 1)];
        else if (row <= 128) v = dWhh1[r * HID + (row - 65)];
    }
    g_W[idx] = v;
}

// ---------------------------------------------------------------------------
// Device helpers
// ---------------------------------------------------------------------------
__device__ __forceinline__ float sigmf(float x) {
    return __fdividef(1.f, 1.f + __expf(-x));
}
// Robust tanh: 1 - 2/(e^{2x}+1). Handles |x| large without NaN.
__device__ __forceinline__ float tanhf_(float x) {
    float e = __expf(2.f * x);
    return 1.f - __fdividef(2.f, e + 1.f);
}

// Packed f32x2 helpers (Blackwell double-rate fp32 path; ptxas never emits
// FFMA2 from plain C++ — must come in via PTX).
__device__ __forceinline__ u64t dup2(float a) {
    u64t r;
    asm("mov.b64 %0, {%1, %1};" : "=l"(r) : "f"(a));
    return r;
}
__device__ __forceinline__ void fma2(u64t& d, u64t a, u64t b) {
    asm("fma.rn.f32x2 %0, %1, %2, %3;" : "=l"(d) : "l"(a), "l"(b), "l"(d));
}
__device__ __forceinline__ float2 unpk(u64t v) {
    float2 r;
    asm("mov.b64 {%0, %1}, %2;" : "=f"(r.x), "=f"(r.y) : "l"(v));
    return r;
}

// GEMM: packed acc[8][4] (pairs along gate columns) += A[K x 64] * B[K x 256].
// B streamed from g_W through a DOUBLE-BUFFERED 16-row SMEM chunk with
// register prefetch: exactly one __syncthreads per chunk.
__device__ __forceinline__ void do_gemm(const float* __restrict__ Bg, int K,
                                        const float* __restrict__ A,
                                        float* __restrict__ Bs,
                                        u64t (&acc)[8][4],
                                        int tid, int tm0, int tn0)
{
    const int nch = (K + KC - 1) >> 4;
    const float4* __restrict__ Bgv = (const float4*)Bg;
    float4* Bsv = (float4*)Bs;       // two buffers of 1024 float4 each
    float4 p0 = Bgv[tid], p1 = Bgv[256 + tid], p2 = Bgv[512 + tid], p3 = Bgv[768 + tid];
    Bsv[tid] = p0; Bsv[256 + tid] = p1; Bsv[512 + tid] = p2; Bsv[768 + tid] = p3;
    __syncthreads();
    for (int c = 0; c < nch; c++) {
        if (c + 1 < nch) {
            const float4* q = Bgv + (size_t)(c + 1) * 1024;
            p0 = q[tid]; p1 = q[256 + tid]; p2 = q[512 + tid]; p3 = q[768 + tid];
        }
        const float* Bsc = Bs + (c & 1) * (KC * NG);
        const int kc   = c * KC;
        const int kend = min(KC, K - kc);
        const float* Abase = A + (size_t)kc * AST;
        #pragma unroll 4
        for (int kk = 0; kk < kend; kk++) {
            float4 a0 = *(const float4*)(Abase + kk * AST + tm0);
            float4 a1 = *(const float4*)(Abase + kk * AST + tm0 + 4);
            ulonglong2 b0 = *(const ulonglong2*)(Bsc + kk * NG + tn0);
            ulonglong2 b1 = *(const ulonglong2*)(Bsc + kk * NG + tn0 + 4);
            u64t bp[4] = {b0.x, b0.y, b1.x, b1.y};
            float av[8] = {a0.x, a0.y, a0.z, a0.w, a1.x, a1.y, a1.z, a1.w};
            #pragma unroll
            for (int i = 0; i < 8; i++) {
                u64t ad = dup2(av[i]);
                #pragma unroll
                for (int p = 0; p < 4; p++)
                    fma2(acc[i][p], ad, bp[p]);
            }
        }
        if (c + 1 < nch) {
            float4* dst = Bsv + (size_t)((c + 1) & 1) * 1024;
            dst[tid] = p0; dst[256 + tid] = p1; dst[512 + tid] = p2; dst[768 + tid] = p3;
        }
        __syncthreads();   // also orders last-chunk reads vs caller's A writes
    }
}

// LSTM gate update. Thread owns 8 rows x 2 hidden cols. Packed acc layout:
// acc[i][p] holds columns (2p, 2p+1); quad jj -> packs (2jj)=(i,f), (2jj+1)=(g,o).
template <bool L0>
__device__ __forceinline__ void do_update(u64t (&acc)[8][4], float (&cst)[8][2],
                                          float* __restrict__ A1w,
                                          float* __restrict__ A0w, int xoff,
                                          int lane, int tm0)
{
    #pragma unroll
    for (int i = 0; i < 8; i++) {
        #pragma unroll
        for (int jj = 0; jj < 2; jj++) {
            float2 g_if = unpk(acc[i][jj * 2 + 0]);
            float2 g_go = unpk(acc[i][jj * 2 + 1]);
            float c = sigmf(g_if.y) * cst[i][jj] + sigmf(g_if.x) * tanhf_(g_go.x);
            cst[i][jj] = c;
            float h = sigmf(g_go.y) * tanhf_(c);
            int j = lane * 2 + jj;
            int m = tm0 + i;
            if (L0) {
                A1w[(1 + j) * AST + m]    = h;   // layer-1 input slot
                A0w[(xoff + j) * AST + m] = h;   // own recurrence slot
            } else {
                A1w[(65 + j) * AST + m]   = h;   // own recurrence slot
            }
        }
    }
}

#define ZERO_ACC(acc) do {                          \
    _Pragma("unroll")                               \
    for (int _i = 0; _i < 8; _i++)                  \
        _Pragma("unroll")                           \
        for (int _p = 0; _p < 4; _p++)              \
            (acc)[_i][_p] = 0ull;                   \
} while (0)

// ---------------------------------------------------------------------------
// Main persistent-per-tile LSTM kernel. One CTA = 64 batch rows, full
// encoder + decoder recurrence with states resident in registers/SMEM.
// ---------------------------------------------------------------------------
__global__ void __launch_bounds__(THREADS)
lstm_main(const float* __restrict__ hist, const float* __restrict__ linW,
          const float* __restrict__ linb, const float* __restrict__ start,
          float* __restrict__ out)
{
    extern __shared__ float sm[];
    float* A0 = sm;                    // [KE0][AST]    layer0 input staging
    float* A1 = A0 + KE0 * AST;        // [KE1][AST]    layer1 input staging
    float* Bs = A1 + KE1 * AST;        // [2][KC][NG]   weight chunk (dbl buf)
    float* lw = Bs + 2 * KC * NG;      // [2][64]       lin_W
    float* lb = lw + 128;              // [2]           lin_b

    const int tid  = threadIdx.x;
    const int lane = tid & 31;
    const int tm0  = (tid >> 5) * 8;
    const int tn0  = lane * 8;
    const int b0   = blockIdx.x * MT;

    for (int i = tid; i < KE0 * AST; i += THREADS) A0[i] = 0.f;
    for (int i = tid; i < KE1 * AST; i += THREADS) A1[i] = 0.f;
    if (tid < MT) { A0[tid] = 1.f; A1[tid] = 1.f; }   // ones row (bias feed)
    if (tid < 128) lw[tid] = linW[tid];
    if (tid < 2)   lb[tid] = linb[tid];

    float cs[2][8][2];
    #pragma unroll
    for (int L = 0; L < 2; L++)
        #pragma unroll
        for (int i = 0; i < 8; i++)
            #pragma unroll
            for (int jj = 0; jj < 2; jj++)
                cs[L][i][jj] = 0.f;
    __syncthreads();

    // ---------------- encoder: 50 steps ----------------
    for (int t = 0; t < SEQ; t++) {
        if (tid < MT) {
            const float* xp = hist + (size_t)(b0 + tid) * (AG * SEQ * IND) + t * IND;
            #pragma unroll
            for (int i = 0; i < IND; i++) A0[(1 + i) * AST + tid] = xp[i];
        }
        __syncthreads();
        u64t acc[8][4];
        ZERO_ACC(acc);
        do_gemm(g_W + OFF_E0, KE0, A0, Bs, acc, tid, tm0, tn0);
        do_update<true>(acc, cs[0], A1, A0, 7, lane, tm0);
        __syncthreads();
        ZERO_ACC(acc);
        do_gemm(g_W + OFF_E1, KE1, A1, Bs, acc, tid, tm0, tn0);
        do_update<false>(acc, cs[1], A1, A0, 0, lane, tm0);
        // next iter's loadx + sync provides the barrier before reuse
    }

    // -------- phase switch: shift h0 rows 7..70 -> 3..66, set start token ----
    {
        __syncthreads();
        float tmp[16];
        #pragma unroll
        for (int e = 0; e < 16; e++) {
            int idx = tid + e * THREADS;       // 0..4095
            int k = idx >> 6, m = idx & 63;
            tmp[e] = A0[(7 + k) * AST + m];
        }
        __syncthreads();
        #pragma unroll
        for (int e = 0; e < 16; e++) {
            int idx = tid + e * THREADS;
            int k = idx >> 6, m = idx & 63;
            A0[(3 + k) * AST + m] = tmp[e];
        }
        if (tid < 128) {
            int o = tid >> 6, m = tid & 63;
            A0[(1 + o) * AST + m] = start[o];
        }
        __syncthreads();
    }

    // ---------------- decoder: 60 steps ----------------
    for (int t = 0; t < TDEC; t++) {
        u64t acc[8][4];
        ZERO_ACC(acc);
        do_gemm(g_W + OFF_D0, KD0, A0, Bs, acc, tid, tm0, tn0);
        do_update<true>(acc, cs[0], A1, A0, 3, lane, tm0);
        __syncthreads();
        ZERO_ACC(acc);
        do_gemm(g_W + OFF_D1, KD1, A1, Bs, acc, tid, tm0, tn0);
        do_update<false>(acc, cs[1], A1, A0, 0, lane, tm0);
        __syncthreads();
        // out = h1 @ lin_W^T + lin_b ; feed back as next x; store result
        if (tid < 128) {
            int o = tid >> 6, m = tid & 63;
            float s = lb[o];
            const float* lwo = lw + o * 64;
            #pragma unroll 8
            for (int k = 0; k < HID; k++)
                s = fmaf(lwo[k], A1[(65 + k) * AST + m], s);
            out[(size_t)(b0 + m) * (TDEC * OUTD) + t * OUTD + o] = s;
            A0[(1 + o) * AST + m] = s;
        }
        __syncthreads();
    }
}

// ---------------------------------------------------------------------------
// Launch
// ---------------------------------------------------------------------------
extern "C" void kernel_launch(void* const* d_in, const int* in_sizes, int n_in,
                              void* d_out, int out_size)
{
    (void)in_sizes; (void)n_in; (void)out_size;
    const float* hist = (const float*)d_in[0];

    prep_kernel<<<(WTOT + 255) / 256, 256>>>(
        (const float*)d_in[1],  (const float*)d_in[2],
        (const float*)d_in[3],  (const float*)d_in[4],
        (const float*)d_in[5],  (const float*)d_in[6],
        (const float*)d_in[7],  (const float*)d_in[8],
        (const float*)d_in[9],  (const float*)d_in[10],
        (const float*)d_in[11], (const float*)d_in[12],
        (const float*)d_in[13], (const float*)d_in[14],
        (const float*)d_in[15], (const float*)d_in[16]);

    size_t smem = (size_t)(KE0 * AST + KE1 * AST + 2 * KC * NG + 132) * sizeof(float);
    cudaFuncSetAttribute(lstm_main, cudaFuncAttributeMaxDynamicSharedMemorySize,
                         (int)smem);
    lstm_main<<<BATCH / MT, THREADS, smem>>>(
        hist, (const float*)d_in[17], (const float*)d_in[18],
        (const float*)d_in[19], (float*)d_out);
}

// round 5
// speedup vs baseline: 1.2037x; 1.1316x over previous
#include <cuda_runtime.h>
#include <math.h>
#include <stdint.h>

#define AG    10
#define SEQ   50
#define IND   6
#define HID   64
#define OUTD  2
#define TDEC  60
#define BATCH 32768

#define NG      256   // 4*HID gate columns
#define MT      128   // batch rows per CTA
#define THREADS 512
#define AST     132   // A staging row stride in floats (pad vs 128)
#define KC      16    // K-chunk rows for weight streaming
#define NBUF    3     // cp.async ring depth

// Logical K per section and padded (multiple of KC) row counts
#define KE0 71
#define KE1 129
#define KD0 67
#define KD1 129
#define PE0 80
#define PE1 144
#define PD0 80
#define PD1 144

#define OFF_E0 0
#define OFF_E1 (PE0*NG)
#define OFF_D0 ((PE0+PE1)*NG)
#define OFF_D1 ((PE0+PE1+PD0)*NG)
#define WTOT   ((PE0+PE1+PD0+PD1)*NG)

typedef unsigned long long u64t;

// Pre-permuted, bias-folded weight scratch (gate-interleaved columns).
__device__ __align__(16) float g_W[WTOT];

// ---------------------------------------------------------------------------
// Prep kernel: build g_W.
// Column n = 4*j + q maps to gate row r = q*64 + j  (q: 0=i,1=f,2=g,3=o).
// Row 0 of each section = combined bias (A supplies a row of ones).
// ---------------------------------------------------------------------------
__global__ void prep_kernel(
    const float* __restrict__ eWih0, const float* __restrict__ eWhh0,
    const float* __restrict__ ebih0, const float* __restrict__ ebhh0,
    const float* __restrict__ eWih1, const float* __restrict__ eWhh1,
    const float* __restrict__ ebih1, const float* __restrict__ ebhh1,
    const float* __restrict__ dWih0, const float* __restrict__ dWhh0,
    const float* __restrict__ dbih0, const float* __restrict__ dbhh0,
    const float* __restrict__ dWih1, const float* __restrict__ dWhh1,
    const float* __restrict__ dbih1, const float* __restrict__ dbhh1)
{
    int idx = blockIdx.x * blockDim.x + threadIdx.x;
    if (idx >= WTOT) return;
    int n    = idx & (NG - 1);
    int grow = idx >> 8;
    int r    = ((n & 3) << 6) | (n >> 2);
    float v = 0.f;
    if (grow < PE0) {
        int row = grow;
        if      (row == 0)  v = ebih0[r] + ebhh0[r];
        else if (row <= 6)  v = eWih0[r * IND + (row - 1)];
        else if (row <= 70) v = eWhh0[r * HID + (row - 7)];
    } else if (grow < PE0 + PE1) {
        int row = grow - PE0;
        if      (row == 0)   v = ebih1[r] + ebhh1[r];
        else if (row <= 64)  v = eWih1[r * HID + (row - 1)];
        else if (row <= 128) v = eWhh1[r * HID + (row - 65)];
    } else if (grow < PE0 + PE1 + PD0) {
        int row = grow - (PE0 + PE1);
        if      (row == 0)  v = dbih0[r] + dbhh0[r];
        else if (row <= 2)  v = dWih0[r * OUTD + (row - 1)];
        else if (row <= 66) v = dWhh0[r * HID + (row - 3)];
    } else {
        int row = grow - (PE0 + PE1 + PD0);
        if      (row == 0)   v = dbih1[r] + dbhh1[r];
        else if (row <= 64)  v = dWih1[r * HID + (row - 1)];
        else if (row <= 128) v = dWhh1[r * HID + (row - 65)];
    }
    g_W[idx] = v;
}

// ---------------------------------------------------------------------------
// Device helpers
// ---------------------------------------------------------------------------
__device__ __forceinline__ float sigmf(float x) {
    return __fdividef(1.f, 1.f + __expf(-x));
}
// Robust tanh: 1 - 2/(e^{2x}+1). Handles |x| large without NaN.
__device__ __forceinline__ float tanhf_(float x) {
    float e = __expf(2.f * x);
    return 1.f - __fdividef(2.f, e + 1.f);
}

// Packed f32x2 helpers (Blackwell double-rate fp32 path).
__device__ __forceinline__ u64t dup2(float a) {
    u64t r;
    asm("mov.b64 %0, {%1, %1};" : "=l"(r) : "f"(a));
    return r;
}
__device__ __forceinline__ void fma2(u64t& d, u64t a, u64t b) {
    asm("fma.rn.f32x2 %0, %1, %2, %3;" : "=l"(d) : "l"(a), "l"(b), "l"(d));
}
__device__ __forceinline__ float2 unpk(u64t v) {
    float2 r;
    asm("mov.b64 {%0, %1}, %2;" : "=f"(r.x), "=f"(r.y) : "l"(v));
    return r;
}

// cp.async 16B global->shared (LDGSTS), L1-bypass.
__device__ __forceinline__ void cpa16(uint32_t saddr, const void* gaddr) {
    asm volatile("cp.async.cg.shared.global [%0], [%1], 16;\n"
                 :: "r"(saddr), "l"(gaddr));
}
#define CPA_COMMIT() asm volatile("cp.async.commit_group;\n" ::: "memory")
#define CPA_WAIT(N)  asm volatile("cp.async.wait_group %0;\n" :: "n"(N) : "memory")

// GEMM: packed acc[8][4] += A[K x 128] * B[K x 256].
// B streamed from g_W via cp.async through a 3-deep 16-row SMEM ring:
// one __syncthreads per chunk, zero staging registers.
__device__ __forceinline__ void do_gemm(const float* __restrict__ Bg, int K,
                                        const float* __restrict__ A,
                                        const float* __restrict__ Bs,
                                        uint32_t bsu,
                                        u64t (&acc)[8][4],
                                        int tid, int tm0, int tn0)
{
    const int nch = (K + KC - 1) >> 4;
    const float4* __restrict__ Bgv = (const float4*)Bg;
    const uint32_t so0 = (uint32_t)tid * 16u;
    const uint32_t so1 = (uint32_t)(THREADS + tid) * 16u;

    // prologue: stage chunks 0 and 1
    cpa16(bsu + so0, Bgv + tid);
    cpa16(bsu + so1, Bgv + THREADS + tid);
    CPA_COMMIT();
    if (nch > 1) {
        uint32_t b1 = bsu + (uint32_t)(KC * NG * 4);
        cpa16(b1 + so0, Bgv + 1024 + tid);
        cpa16(b1 + so1, Bgv + 1024 + THREADS + tid);
        CPA_COMMIT();
    }

    for (int c = 0; c < nch; c++) {
        if (c + 1 < nch) CPA_WAIT(1); else CPA_WAIT(0);
        __syncthreads();                       // chunk c visible to all
        if (c + 2 < nch) {                     // stage chunk c+2 into ring
            uint32_t bd = bsu + (uint32_t)(((c + 2) % NBUF) * (KC * NG * 4));
            const float4* q = Bgv + (size_t)(c + 2) * 1024;
            cpa16(bd + so0, q + tid);
            cpa16(bd + so1, q + THREADS + tid);
            CPA_COMMIT();
        }
        const float* Bsc = Bs + (c % NBUF) * (KC * NG);
        const int kc   = c * KC;
        const int kend = min(KC, K - kc);
        const float* Abase = A + (size_t)kc * AST;
        #pragma unroll 4
        for (int kk = 0; kk < kend; kk++) {
            float4 a0 = *(const float4*)(Abase + kk * AST + tm0);
            float4 a1 = *(const float4*)(Abase + kk * AST + tm0 + 4);
            ulonglong2 b0 = *(const ulonglong2*)(Bsc + kk * NG + tn0);
            ulonglong2 b1 = *(const ulonglong2*)(Bsc + kk * NG + tn0 + 4);
            u64t bp[4] = {b0.x, b0.y, b1.x, b1.y};
            float av[8] = {a0.x, a0.y, a0.z, a0.w, a1.x, a1.y, a1.z, a1.w};
            #pragma unroll
            for (int i = 0; i < 8; i++) {
                u64t ad = dup2(av[i]);
                #pragma unroll
                for (int p = 0; p < 4; p++)
                    fma2(acc[i][p], ad, bp[p]);
            }
        }
        __syncthreads();   // all reads of this chunk (and, on the last
                           // chunk, of A) done before buffers are reused
    }
}

// LSTM gate update. Thread owns 8 rows x 2 hidden cols. Packed acc layout:
// acc[i][p] holds cols (2p,2p+1); quad jj -> packs (2jj)=(i,f), (2jj+1)=(g,o).
// Cell state lives in SMEM (float2 per (i) per thread), registers stay lean.
template <bool L0>
__device__ __forceinline__ void do_update(u64t (&acc)[8][4],
                                          float2* __restrict__ csL,
                                          float* __restrict__ A1w,
                                          float* __restrict__ A0w, int xoff,
                                          int lane, int tm0)
{
    #pragma unroll
    for (int i = 0; i < 8; i++) {
        float2 cv = csL[i * THREADS];
        #pragma unroll
        for (int jj = 0; jj < 2; jj++) {
            float2 g_if = unpk(acc[i][jj * 2 + 0]);
            float2 g_go = unpk(acc[i][jj * 2 + 1]);
            float cprev = (jj == 0) ? cv.x : cv.y;
            float c = sigmf(g_if.y) * cprev + sigmf(g_if.x) * tanhf_(g_go.x);
            if (jj == 0) cv.x = c; else cv.y = c;
            float h = sigmf(g_go.y) * tanhf_(c);
            int j = lane * 2 + jj;
            int m = tm0 + i;
            if (L0) {
                A1w[(1 + j) * AST + m]    = h;   // layer-1 input slot
                A0w[(xoff + j) * AST + m] = h;   // own recurrence slot
            } else {
                A1w[(65 + j) * AST + m]   = h;   // own recurrence slot
            }
        }
        csL[i * THREADS] = cv;
    }
}

#define ZERO_ACC(acc) do {                          \
    _Pragma("unroll")                               \
    for (int _i = 0; _i < 8; _i++)                  \
        _Pragma("unroll")                           \
        for (int _p = 0; _p < 4; _p++)              \
            (acc)[_i][_p] = 0ull;                   \
} while (0)

// SMEM float counts
#define SM_A0  (KE0*AST)
#define SM_A1  (KE1*AST)
#define SM_BS  (NBUF*KC*NG)
#define SM_CS  (2*8*THREADS*2)
#define SM_TOT (SM_A0 + SM_A1 + SM_BS + SM_CS + 130)

// ---------------------------------------------------------------------------
// Main persistent-per-tile LSTM kernel. One CTA = 128 batch rows, 16 warps,
// full encoder + decoder recurrence with states resident in SMEM/registers.
// ---------------------------------------------------------------------------
__global__ void __launch_bounds__(THREADS, 1)
lstm_main(const float* __restrict__ hist, const float* __restrict__ linW,
          const float* __restrict__ linb, const float* __restrict__ start,
          float* __restrict__ out)
{
    extern __shared__ float sm[];
    float*  A0  = sm;                     // [KE0][AST]      layer0 input staging
    float*  A1  = A0 + SM_A0;             // [KE1][AST]      layer1 input staging
    float*  Bs  = A1 + SM_A1;             // [NBUF][KC][NG]  weight ring
    float*  csf = Bs + SM_BS;             // [2][8][THREADS] float2 cell state
    float*  lw  = csf + SM_CS;            // [2][64]         lin_W
    float*  lb  = lw + 128;               // [2]             lin_b

    const int tid  = threadIdx.x;
    const int lane = tid & 31;
    const int tm0  = (tid >> 5) * 8;
    const int tn0  = lane * 8;
    const int b0   = blockIdx.x * MT;

    uint32_t bsu;
    asm("{ .reg .u64 t; cvta.to.shared.u64 t, %1; cvt.u32.u64 %0, t; }"
        : "=r"(bsu) : "l"(Bs));

    float2* cs0 = (float2*)csf + tid;              // layer-0 state
    float2* cs1 = (float2*)csf + 8 * THREADS + tid; // layer-1 state

    for (int i = tid; i < SM_A0; i += THREADS) A0[i] = 0.f;
    for (int i = tid; i < SM_A1; i += THREADS) A1[i] = 0.f;
    for (int i = tid; i < SM_CS; i += THREADS) csf[i] = 0.f;
    if (tid < MT) { A0[tid] = 1.f; A1[tid] = 1.f; }   // ones row (bias feed)
    if (tid < 128) lw[tid] = linW[tid];
    if (tid < 2)   lb[tid] = linb[tid];
    __syncthreads();

    // ---------------- encoder: 50 steps ----------------
    for (int t = 0; t < SEQ; t++) {
        if (tid < MT) {
            const float* xp = hist + (size_t)(b0 + tid) * (AG * SEQ * IND) + t * IND;
            #pragma unroll
            for (int i = 0; i < IND; i++) A0[(1 + i) * AST + tid] = xp[i];
        }
        u64t acc[8][4];
        ZERO_ACC(acc);
        do_gemm(g_W + OFF_E0, KE0, A0, Bs, bsu, acc, tid, tm0, tn0);
        do_update<true>(acc, cs0, A1, A0, 7, lane, tm0);
        ZERO_ACC(acc);
        do_gemm(g_W + OFF_E1, KE1, A1, Bs, bsu, acc, tid, tm0, tn0);
        do_update<false>(acc, cs1, A1, A0, 0, lane, tm0);
        // next gemm's chunk-0 barrier orders these writes
    }

    // -------- phase switch: shift h0 rows 7..70 -> 3..66, set start token ----
    {
        __syncthreads();
        float tmp[16];
        #pragma unroll
        for (int e = 0; e < 16; e++) {
            int idx = tid + e * THREADS;       // 0..8191
            int k = idx >> 7, m = idx & 127;
            tmp[e] = A0[(7 + k) * AST + m];
        }
        __syncthreads();
        #pragma unroll
        for (int e = 0; e < 16; e++) {
            int idx = tid + e * THREADS;
            int k = idx >> 7, m = idx & 127;
            A0[(3 + k) * AST + m] = tmp[e];
        }
        if (tid < 2 * MT) {
            int o = tid >> 7, m = tid & 127;
            A0[(1 + o) * AST + m] = start[o];
        }
        __syncthreads();
    }

    // ---------------- decoder: 60 steps ----------------
    for (int t = 0; t < TDEC; t++) {
        u64t acc[8][4];
        ZERO_ACC(acc);
        do_gemm(g_W + OFF_D0, KD0, A0, Bs, bsu, acc, tid, tm0, tn0);
        do_update<true>(acc, cs0, A1, A0, 3, lane, tm0);
        ZERO_ACC(acc);
        do_gemm(g_W + OFF_D1, KD1, A1, Bs, bsu, acc, tid, tm0, tn0);
        do_update<false>(acc, cs1, A1, A0, 0, lane, tm0);
        __syncthreads();
        // out = h1 @ lin_W^T + lin_b ; feed back as next x; store result
        if (tid < 2 * MT) {
            int o = tid >> 7, m = tid & 127;
            float s = lb[o];
            const float* lwo = lw + o * 64;
            #pragma unroll 8
            for (int k = 0; k < HID; k++)
                s = fmaf(lwo[k], A1[(65 + k) * AST + m], s);
            out[(size_t)(b0 + m) * (TDEC * OUTD) + t * OUTD + o] = s;
            A0[(1 + o) * AST + m] = s;
        }
        __syncthreads();
    }
}

// ---------------------------------------------------------------------------
// Launch
// ---------------------------------------------------------------------------
extern "C" void kernel_launch(void* const* d_in, const int* in_sizes, int n_in,
                              void* d_out, int out_size)
{
    (void)in_sizes; (void)n_in; (void)out_size;
    const float* hist = (const float*)d_in[0];

    prep_kernel<<<(WTOT + 255) / 256, 256>>>(
        (const float*)d_in[1],  (const float*)d_in[2],
        (const float*)d_in[3],  (const float*)d_in[4],
        (const float*)d_in[5],  (const float*)d_in[6],
        (const float*)d_in[7],  (const float*)d_in[8],
        (const float*)d_in[9],  (const float*)d_in[10],
        (const float*)d_in[11], (const float*)d_in[12],
        (const float*)d_in[13], (const float*)d_in[14],
        (const float*)d_in[15], (const float*)d_in[16]);

    size_t smem = (size_t)SM_TOT * sizeof(float);
    cudaFuncSetAttribute(lstm_main, cudaFuncAttributeMaxDynamicSharedMemorySize,
                         (int)smem);
    lstm_main<<<BATCH / MT, THREADS, smem>>>(
        hist, (const float*)d_in[17], (const float*)d_in[18],
        (const float*)d_in[19], (float*)d_out);
}